// round 17
// baseline (speedup 1.0000x reference)
#include <cuda_runtime.h>
#include <cuda_fp16.h>
#include <cstdint>

// ===========================================================================
// MeshGraphEdgeMLPSum — single persistent kernel, 3 phases w/ grid barriers:
//   P0: round all 4 weight matrices to fp16 (staged in gmem, padded stride)
//   P1: node projections  P[n] = fp16[ nfeat@Ws^T | nfeat@Wd^T + b1 ]
//   P2: edge pipeline      out = LN( silu(ef@We^T + Ps[src]+Pd[dst]) @ W2^T + b2 )
// fp16 1-term GEMMs, fp32 accumulate, mma.sync.m16n8k16.f16 + ldmatrix.x4.
// R16: phase 2 = FOUR independent 128-thread pipelines (one named barrier
// each), 32-row tiles, all dependencies pipeline-local -> 4-way phase overlap.
// tanh SiLU, ldsm/stsm epilogue-1, cp.async gathers, double-buffered Act.
// ===========================================================================

#define LDW 136   // padded fp16 row stride (272 B): ldmatrix/LDS conflict-free
#define NT  512   // threads per CTA
#define MATB (128 * LDW * 2)   // 34816 B per fp16 matrix
#define HSLAB (32 * LDW)       // 32-row pipeline slab (halves)

// ------------------------- globals ----------------------------------------
__device__ __half g_W[4][128 * LDW];   // We, W2, Ws, Wd (fp16, padded)
__device__ __half g_P[50048 * 256];    // [node][0:128]=src proj, [128:256]=dst+b1
__device__ unsigned int g_cnt = 0;     // monotone grid-barrier counter

// ------------------------- smem layout ------------------------------------
#define SM_W     0                       // 2 matrices (per phase) = 69632
#define SM_ACT   69632                   // 2 parity x 4 pipe x 8704 = 69632
#define SM_PS    139264                  // gather stage src: 4 x 8704
#define SM_PD    174080                  // gather stage dst: 4 x 8704
#define SM_RED   208896                  // float2[128*4] = 4096
#define SM_B2    212992
#define SM_G     213504
#define SM_BT    214016
#define SM_B1    214528
#define SMEM_SZ  215552

// ------------------------- helpers ----------------------------------------
__device__ __forceinline__ uint32_t smem_u32(const void* p) {
    uint32_t a;
    asm("{ .reg .u64 t; cvta.to.shared.u64 t, %1; cvt.u32.u64 %0, t; }" : "=r"(a) : "l"(p));
    return a;
}

__device__ __forceinline__ void ldsm4(uint32_t* r, uint32_t addr) {
    asm volatile("ldmatrix.sync.aligned.m8n8.x4.shared.b16 {%0,%1,%2,%3}, [%4];"
        : "=r"(r[0]), "=r"(r[1]), "=r"(r[2]), "=r"(r[3]) : "r"(addr));
}

__device__ __forceinline__ void stsm4(uint32_t addr, uint32_t v0, uint32_t v1,
                                      uint32_t v2, uint32_t v3) {
    asm volatile("stmatrix.sync.aligned.m8n8.x4.shared.b16 [%0], {%1,%2,%3,%4};"
        :: "r"(addr), "r"(v0), "r"(v1), "r"(v2), "r"(v3) : "memory");
}

__device__ __forceinline__ void mma_f16(float* c, const uint32_t* a, uint32_t b0, uint32_t b1) {
    asm volatile(
        "mma.sync.aligned.m16n8k16.row.col.f32.f16.f16.f32 "
        "{%0,%1,%2,%3}, {%4,%5,%6,%7}, {%8,%9}, {%0,%1,%2,%3};\n"
        : "+f"(c[0]), "+f"(c[1]), "+f"(c[2]), "+f"(c[3])
        : "r"(a[0]), "r"(a[1]), "r"(a[2]), "r"(a[3]), "r"(b0), "r"(b1));
}

__device__ __forceinline__ float silu_f(float x) {
    float h = 0.5f * x, t;
    asm("tanh.approx.f32 %0, %1;" : "=f"(t) : "f"(h));
    return fmaf(h, t, h);   // 0.5x·(1+tanh(x/2)) = x·sigmoid(x)
}

__device__ __forceinline__ void cp16(uint32_t dst, const void* src) {
    asm volatile("cp.async.cg.shared.global [%0], [%1], 16;" :: "r"(dst), "l"(src));
}
#define CP_COMMIT() asm volatile("cp.async.commit_group;" ::: "memory")
#define CP_WAIT0()  asm volatile("cp.async.wait_group 0;" ::: "memory")

// pipeline barrier: named barrier (id = pipe+1), 128 threads
__device__ __forceinline__ void pbar(int pipe) {
    asm volatile("bar.sync %0, 128;" :: "r"(pipe + 1) : "memory");
}

// monotone grid barrier: no reset needed across graph replays
__device__ __forceinline__ void grid_barrier(int nctas) {
    __syncthreads();
    if (threadIdx.x == 0) {
        __threadfence();
        unsigned int t = atomicAdd(&g_cnt, 1u) + 1u;
        unsigned int target = ((t + (unsigned)nctas - 1u) / (unsigned)nctas) * (unsigned)nctas;
        unsigned int cur;
        do {
            asm volatile("ld.acquire.gpu.u32 %0, [%1];" : "=r"(cur) : "l"(&g_cnt));
        } while (cur < target);
    }
    __syncthreads();
}

// acc += A @ W^T : fp16 1-term, ldmatrix.x4 fragments. Warp tile 32x32.
__device__ __forceinline__ void gemm1(
    const __half* A, const __half* W,
    float acc[2][4][4], int mbase, int nbase, int lane)
{
    const int rowA = lane & 15;
    const int colA = (lane >> 4) << 3;
    uint32_t aA = smem_u32(A) + (uint32_t)(((mbase + rowA) * LDW + colA) * 2);
    const int rowB = (lane & 7) + ((lane & 16) >> 1);
    const int colB = lane & 8;
    uint32_t aB = smem_u32(W) + (uint32_t)(((nbase + rowB) * LDW + colB) * 2);
    const uint32_t MI = 16 * LDW * 2;

    #pragma unroll
    for (int k0 = 0; k0 < 128; k0 += 16) {
        uint32_t a0[4], a1[4], b[2][4];
        ldsm4(a0, aA + k0 * 2);
        ldsm4(a1, aA + MI + k0 * 2);
        ldsm4(b[0], aB + k0 * 2);
        ldsm4(b[1], aB + MI + k0 * 2);
        #pragma unroll
        for (int ni = 0; ni < 4; ni++) {
            mma_f16(acc[0][ni], a0, b[ni >> 1][(ni & 1) * 2], b[ni >> 1][(ni & 1) * 2 + 1]);
            mma_f16(acc[1][ni], a1, b[ni >> 1][(ni & 1) * 2], b[ni >> 1][(ni & 1) * 2 + 1]);
        }
    }
}

__device__ __forceinline__ void zero_acc(float acc[2][4][4]) {
    #pragma unroll
    for (int mi = 0; mi < 2; mi++)
        #pragma unroll
        for (int ni = 0; ni < 4; ni++)
            #pragma unroll
            for (int j = 0; j < 4; j++)
                acc[mi][ni][j] = 0.f;
}

// ---- phase-2 building blocks (32-row pipeline tiles) ----------------------
__device__ __forceinline__ void load_efeat_p(const float* __restrict__ efeat,
                                             __half* dst, int base, int ptid, int E)
{
    #pragma unroll 4
    for (int i = ptid; i < 32 * 32; i += 128) {
        int r = i >> 5, c4 = (i & 31) * 4;
        int e = base + r;
        float4 v = make_float4(0.f, 0.f, 0.f, 0.f);
        if (e < E) v = *(const float4*)(efeat + (size_t)e * 128 + c4);
        __half2 h0 = __floats2half2_rn(v.x, v.y);
        __half2 h1 = __floats2half2_rn(v.z, v.w);
        uint2 pk = make_uint2(*(uint32_t*)&h0, *(uint32_t*)&h1);
        *(uint2*)(dst + r * LDW + c4) = pk;
    }
}

__device__ __forceinline__ void issue_gathers_p(const int* __restrict__ src_idx,
                                                const int* __restrict__ dst_idx,
                                                uint32_t psb, uint32_t pdb,
                                                int base, int ptid, int E)
{
    // 32 rows x {src,dst} x 2 half-rows = 128 tasks, one per thread
    int r = (ptid & 63) >> 1, hf = ptid & 1;
    int e = base + r;
    if (ptid < 64) {
        int node = (e < E) ? src_idx[e] : 0;
        const char* srcp = (const char*)g_P + (size_t)node * 512 + hf * 128;
        uint32_t dstp = psb + (uint32_t)(r * 272 + hf * 128);
        #pragma unroll
        for (int j = 0; j < 8; j++) cp16(dstp + j * 16, srcp + j * 16);
    } else {
        int node = (e < E) ? dst_idx[e] : 0;
        const char* srcp = (const char*)g_P + (size_t)node * 512 + 256 + hf * 128;
        uint32_t dstp = pdb + (uint32_t)(r * 272 + hf * 128);
        #pragma unroll
        for (int j = 0; j < 8; j++) cp16(dstp + j * 16, srcp + j * 16);
    }
    CP_COMMIT();
}

// ------------------------- the fused persistent kernel --------------------
__global__ __launch_bounds__(NT, 1)
void fused_kernel(const float* __restrict__ efeat, const float* __restrict__ nfeat,
                  const int* __restrict__ src_idx, const int* __restrict__ dst_idx,
                  const float* __restrict__ w_efeat, const float* __restrict__ w_src,
                  const float* __restrict__ w_dst,  const float* __restrict__ b1,
                  const float* __restrict__ w2,     const float* __restrict__ b2,
                  const float* __restrict__ ln_g,   const float* __restrict__ ln_b,
                  float* __restrict__ out, int E, int Nn)
{
    extern __shared__ char sm[];
    __half* Wsm   = (__half*)(sm + SM_W);
    __half* ActA  = (__half*)(sm + SM_ACT);     // [parity*4+pipe] 32-row slabs
    __half* Ps_s  = (__half*)(sm + SM_PS);
    __half* Pd_s  = (__half*)(sm + SM_PD);
    float2* s_red = (float2*)(sm + SM_RED);     // [(pipe*32+r)*4 + nquad]
    float*  s_b2  = (float*)(sm + SM_B2);
    float*  s_g   = (float*)(sm + SM_G);
    float*  s_bt  = (float*)(sm + SM_BT);
    float*  s_b1  = (float*)(sm + SM_B1);

    const int tid = threadIdx.x;
    const int nctas = gridDim.x;
    const int warp = tid >> 5, lane = tid & 31, g = lane >> 2, t = lane & 3;

    // ---------------- phase 0: weight rounding (fp16, padded) -----------
    {
        const float* srcs[4] = { w_efeat, w2, w_src, w_dst };
        for (int i = blockIdx.x * NT + tid; i < 4 * 16384; i += nctas * NT) {
            int mat = i >> 14, idx = i & 16383;
            int r = idx >> 7, c = idx & 127;
            g_W[mat][r * LDW + c] = __float2half(srcs[mat][r * 128 + c]);
        }
    }
    grid_barrier(nctas);

    // ---------------- phase 1: node projections -> fp16 P ---------------
    {
        __half* Act = ActA;   // parity-0 slabs are contiguous 128 rows
        const int mbase = (warp >> 2) * 32, nbase = (warp & 3) * 32;
        const uint4* s = (const uint4*)g_W[2];   // Ws, Wd
        uint4* d = (uint4*)Wsm;
        for (int i = tid; i < 2 * MATB / 16; i += NT) d[i] = s[i];
        if (tid < 128) s_b1[tid] = b1[tid];
        __syncthreads();

        const int ntile = (Nn + 127) >> 7;
        for (int tile = blockIdx.x; tile < ntile; tile += nctas) {
            const int base = tile << 7;
            __syncthreads();  // prev tile's gemm reads of Act done

            #pragma unroll 2
            for (int i = tid; i < 128 * 32; i += NT) {
                int r = i >> 5, c4 = (i & 31) * 4;
                int node = base + r;
                float4 v = make_float4(0.f, 0.f, 0.f, 0.f);
                if (node < Nn) v = *(const float4*)(nfeat + (size_t)node * 128 + c4);
                __half2 h0 = __floats2half2_rn(v.x, v.y);
                __half2 h1 = __floats2half2_rn(v.z, v.w);
                uint2 pk = make_uint2(*(uint32_t*)&h0, *(uint32_t*)&h1);
                *(uint2*)(Act + r * LDW + c4) = pk;
            }
            __syncthreads();

            #pragma unroll
            for (int half = 0; half < 2; half++) {
                float acc[2][4][4];
                zero_acc(acc);
                gemm1(Act, Wsm + half * 128 * LDW, acc, mbase, nbase, lane);
                #pragma unroll
                for (int mi = 0; mi < 2; mi++) {
                    int r0 = mbase + mi * 16 + g;
                    int n0 = base + r0, n1 = n0 + 8;
                    #pragma unroll
                    for (int ni = 0; ni < 4; ni++) {
                        int col = nbase + ni * 8 + t * 2;
                        float bx = half ? s_b1[col]     : 0.f;
                        float by = half ? s_b1[col + 1] : 0.f;
                        if (n0 < Nn)
                            *(__half2*)(g_P + (size_t)n0 * 256 + half * 128 + col) =
                                __floats2half2_rn(acc[mi][ni][0] + bx, acc[mi][ni][1] + by);
                        if (n1 < Nn)
                            *(__half2*)(g_P + (size_t)n1 * 256 + half * 128 + col) =
                                __floats2half2_rn(acc[mi][ni][2] + bx, acc[mi][ni][3] + by);
                    }
                }
            }
        }
    }
    grid_barrier(nctas);

    // ---------------- phase 2: FOUR independent 128-thread pipelines ----
    {
        const uint4* s = (const uint4*)g_W[0];   // We, W2
        uint4* d = (uint4*)Wsm;
        for (int i = tid; i < 2 * MATB / 16; i += NT) d[i] = s[i];
        if (tid < 128) { s_b2[tid] = b2[tid]; s_g[tid] = ln_g[tid]; s_bt[tid] = ln_b[tid]; }
        __syncthreads();   // weights + consts visible to all pipelines

        const int pipe = tid >> 7;           // 0..3
        const int ptid = tid & 127;
        const int pw   = ptid >> 5;          // warp in pipeline, 0..3
        const int nb   = pw * 32;            // warp's 32-col N slice

        __half* buf[2] = { ActA + (0 * 4 + pipe) * HSLAB, ActA + (1 * 4 + pipe) * HSLAB };
        __half* PsP  = Ps_s + pipe * HSLAB;
        __half* PdP  = Pd_s + pipe * HSLAB;
        const uint32_t psb = smem_u32(PsP), pdb = smem_u32(PdP);

        // fragment lane addressing for ldsm/stsm in epilogue 1 (mb = 0):
        const int fr = lane & 7, fc = (lane >> 3) << 3;
        const uint32_t foff = (uint32_t)(fr * 272 + (nb + fc) * 2);
        const uint32_t fps = psb + foff, fpd = pdb + foff;
        const uint32_t hb[2] = { smem_u32(buf[0]) + foff, smem_u32(buf[1]) + foff };

        const int step = nctas * 4;
        const int ntiles = (E + 31) >> 5;    // 32-row tiles
        int tile = blockIdx.x * 4 + pipe;
        int p = 0;

        // prologue: prefetch first tile
        if (tile < ntiles) {
            issue_gathers_p(src_idx, dst_idx, psb, pdb, tile << 5, ptid, E);
            load_efeat_p(efeat, buf[p], tile << 5, ptid, E);
        }

        for (; tile < ntiles; tile += step) {
            const int base = tile << 5;
            pbar(pipe);   // efeat(buf[p]) visible; prev tile fully consumed

            // ---- GEMM1: efeat @ We^T (gathers in flight)
            float acc[2][4][4];
            zero_acc(acc);
            gemm1(buf[p], Wsm, acc, 0, nb, lane);

            CP_WAIT0();
            pbar(pipe);   // pipeline: GEMM1 done + gathers visible

            // ---- epilogue 1: + Ps + Pd (ldsm), tanh-SiLU, hidden -> buf[p] (stsm)
            #pragma unroll
            for (int mi = 0; mi < 2; mi++) {
                const uint32_t o = (uint32_t)(mi * 16 * 272);
                uint32_t ps0[4], ps1[4], pd0[4], pd1[4];
                ldsm4(ps0, fps + o);
                ldsm4(ps1, fps + o + 8 * 272);
                ldsm4(pd0, fpd + o);
                ldsm4(pd1, fpd + o + 8 * 272);
                uint32_t v0[4], v1[4];
                #pragma unroll
                for (int ni = 0; ni < 4; ni++) {
                    __half2 q0h = __hadd2(*(__half2*)&ps0[ni], *(__half2*)&pd0[ni]);
                    __half2 q1h = __hadd2(*(__half2*)&ps1[ni], *(__half2*)&pd1[ni]);
                    float2 q0 = __half22float2(q0h);
                    float2 q1 = __half22float2(q1h);
                    float x0 = silu_f(acc[mi][ni][0] + q0.x);
                    float x1 = silu_f(acc[mi][ni][1] + q0.y);
                    float x2 = silu_f(acc[mi][ni][2] + q1.x);
                    float x3 = silu_f(acc[mi][ni][3] + q1.y);
                    __half2 h0 = __floats2half2_rn(x0, x1);
                    __half2 h1 = __floats2half2_rn(x2, x3);
                    v0[ni] = *(uint32_t*)&h0;
                    v1[ni] = *(uint32_t*)&h1;
                }
                stsm4(hb[p] + o,           v0[0], v0[1], v0[2], v0[3]);
                stsm4(hb[p] + o + 8 * 272, v1[0], v1[1], v1[2], v1[3]);
            }
            pbar(pipe);

            // ---- GEMM2: hidden @ W2^T
            zero_acc(acc);
            gemm1(buf[p], Wsm + 128 * LDW, acc, 0, nb, lane);

            // ---- +b2, per-row partial sums -> smem combine (pipeline rows)
            #pragma unroll
            for (int mi = 0; mi < 2; mi++) {
                #pragma unroll
                for (int hr = 0; hr < 2; hr++) {
                    float ss = 0.f, s2 = 0.f;
                    #pragma unroll
                    for (int ni = 0; ni < 4; ni++) {
                        int col = nb + ni * 8 + t * 2;
                        float x0 = acc[mi][ni][hr * 2]     + s_b2[col];
                        float x1 = acc[mi][ni][hr * 2 + 1] + s_b2[col + 1];
                        acc[mi][ni][hr * 2]     = x0;
                        acc[mi][ni][hr * 2 + 1] = x1;
                        ss += x0 + x1;
                        s2 += x0 * x0 + x1 * x1;
                    }
                    ss += __shfl_xor_sync(0xffffffffu, ss, 1);
                    s2 += __shfl_xor_sync(0xffffffffu, s2, 1);
                    ss += __shfl_xor_sync(0xffffffffu, ss, 2);
                    s2 += __shfl_xor_sync(0xffffffffu, s2, 2);
                    if (t == 0) {
                        int r = mi * 16 + g + hr * 8;
                        s_red[(pipe * 32 + r) * 4 + pw] = make_float2(ss, s2);
                    }
                }
            }
            pbar(pipe);

            // ---- prefetch NEXT tile (gathers + efeat) while LN runs below
            int ntl = tile + step;
            if (ntl < ntiles) {
                issue_gathers_p(src_idx, dst_idx, psb, pdb, ntl << 5, ptid, E);
                load_efeat_p(efeat, buf[p ^ 1], ntl << 5, ptid, E);
            }

            // ---- LayerNorm + store straight from accumulators
            #pragma unroll
            for (int mi = 0; mi < 2; mi++) {
                #pragma unroll
                for (int hr = 0; hr < 2; hr++) {
                    int r = mi * 16 + g + hr * 8;
                    const float2* pr = &s_red[(pipe * 32 + r) * 4];
                    float2 p0 = pr[0], p1 = pr[1], p2 = pr[2], p3 = pr[3];
                    float ssum = (p0.x + p1.x) + (p2.x + p3.x);
                    float ssq  = (p0.y + p1.y) + (p2.y + p3.y);
                    float mean = ssum * (1.f / 128.f);
                    float var  = ssq * (1.f / 128.f) - mean * mean;
                    float rstd = rsqrtf(var + 1e-5f);
                    int e = base + r;
                    if (e < E) {
                        float* po = out + (size_t)e * 128;
                        #pragma unroll
                        for (int ni = 0; ni < 4; ni++) {
                            int col = nb + ni * 8 + t * 2;
                            float2 v;
                            v.x = (acc[mi][ni][hr * 2]     - mean) * rstd * s_g[col]     + s_bt[col];
                            v.y = (acc[mi][ni][hr * 2 + 1] - mean) * rstd * s_g[col + 1] + s_bt[col + 1];
                            *(float2*)(po + col) = v;
                        }
                    }
                }
            }

            p ^= 1;
        }
    }
}

// ---------------------------------------------------------------------------
extern "C" void kernel_launch(void* const* d_in, const int* in_sizes, int n_in,
                              void* d_out, int out_size)
{
    const float* efeat   = (const float*)d_in[0];
    const float* nfeat   = (const float*)d_in[1];
    const int*   src_idx = (const int*)d_in[2];
    const int*   dst_idx = (const int*)d_in[3];
    const float* w_efeat = (const float*)d_in[4];
    const float* w_src   = (const float*)d_in[5];
    const float* w_dst   = (const float*)d_in[6];
    const float* b1      = (const float*)d_in[7];
    const float* w2      = (const float*)d_in[8];
    const float* b2      = (const float*)d_in[9];
    const float* ln_g    = (const float*)d_in[10];
    const float* ln_b    = (const float*)d_in[11];
    float* out = (float*)d_out;

    const int E = in_sizes[2];
    const int N = in_sizes[1] / 128;

    cudaFuncSetAttribute(fused_kernel, cudaFuncAttributeMaxDynamicSharedMemorySize, SMEM_SZ);

    // 1 CTA/SM persistent grid; fewer CTAs than SMs stays safe for the barrier.
    int nsm = 148;
    if (cudaDeviceGetAttribute(&nsm, cudaDevAttrMultiProcessorCount, 0) != cudaSuccess || nsm <= 0)
        nsm = 148;

    fused_kernel<<<nsm, NT, SMEM_SZ>>>(efeat, nfeat, src_idx, dst_idx,
                                       w_efeat, w_src, w_dst, b1, w2, b2,
                                       ln_g, ln_b, out, E, N);
}